// round 7
// baseline (speedup 1.0000x reference)
#include <cuda_runtime.h>
#include <cuda_bf16.h>
#include <math.h>
#include <stdint.h>

typedef unsigned long long U64;

// Problem constants
#define BB   4
#define CC   128
#define HH   96
#define WW   96
#define HWX  (HH*WW)          // 9216
#define CHW  (CC*HWX)         // 1179648
#define CO   256
#define KTOT (CC*9)           // 1152
#define NITER 18
#define KC    64              // K floats per iter

// Scratch (device globals)
__device__ float g_off [BB*18*HWX];
__device__ float g_mask[BB*9*HWX];
// Pre-split, pre-swizzled A tiles: [18 iters][hi 32KB | lo 32KB], SW128 rows.
__device__ __align__(16) unsigned char g_wtsm[NITER * 65536];

// SMEM layout (dynamic), occ-1 double buffered
#define OFF_A0 0          // A buf0: hi 16384 | lo 16384 (this block's Co half)
#define OFF_A1 32768
#define OFF_B0 65536      // B buf0: hi 16384 | lo 16384
#define OFF_B1 98304
#define OFF_PI 131072     // 9*128*4  = 4608
#define OFF_PW 135680     // 9*128*16 = 18432
#define SMEM_SZ 154112

union F2U { U64 u; float2 f; };

__device__ __forceinline__ U64 pk2(float a, float b) {
    U64 r; asm("mov.b64 %0, {%1, %2};" : "=l"(r) : "f"(a), "f"(b)); return r;
}
__device__ __forceinline__ void fma2(U64 &d, U64 a, U64 b) {
    asm("fma.rn.f32x2 %0, %1, %2, %3;" : "=l"(d) : "l"(a), "l"(b), "l"(d));
}
__device__ __forceinline__ unsigned s2u(const void* p) {
    return (unsigned)__cvta_generic_to_shared(p);
}
__device__ __forceinline__ void cpa16(unsigned dst, const void* src) {
    asm volatile("cp.async.cg.shared.global [%0], [%1], 16;" :: "r"(dst), "l"(src));
}
#define CP_COMMIT()  asm volatile("cp.async.commit_group;" ::: "memory")
#define CP_WAIT0()   asm volatile("cp.async.wait_group 0;" ::: "memory")

#define LDSM4(r0, r1, r2, r3, addr) \
    asm volatile("ldmatrix.sync.aligned.m8n8.x4.shared.b16 {%0,%1,%2,%3}, [%4];" \
        : "=r"(r0), "=r"(r1), "=r"(r2), "=r"(r3) : "r"(addr))

#define MMA(d, a0, a1, a2, a3, b0, b1) \
    asm volatile("mma.sync.aligned.m16n8k16.row.col.f32.bf16.bf16.f32 " \
        "{%0,%1,%2,%3}, {%4,%5,%6,%7}, {%8,%9}, {%0,%1,%2,%3};" \
        : "+f"((d)[0]), "+f"((d)[1]), "+f"((d)[2]), "+f"((d)[3]) \
        : "r"(a0), "r"(a1), "r"(a2), "r"(a3), "r"(b0), "r"(b1))

// ---------------------------------------------------------------------------
// Kernel 0: pre-split weights into bf16 hi/lo, pre-swizzled SW128 tile images.
// ---------------------------------------------------------------------------
__global__ void k_wt(const float* __restrict__ w) {
    int i = blockIdx.x * 256 + threadIdx.x;
    int o  = i / 288;
    int r4 = (i - o * 288) * 4;
    float4 wv = *(const float4*)(w + o * KTOT + r4);
    int t  = r4 >> 6;
    int kk = r4 & 63;
    unsigned rowbase = (o & 7) * 128;
    unsigned off = (unsigned)(o >> 3) * 1024
                 + ((rowbase + kk * 2) ^ ((rowbase >> 3) & 0x70));
    const float* fv = (const float*)&wv;
    U64 hi = 0, lo = 0;
#pragma unroll
    for (int e = 0; e < 4; ++e) {
        __nv_bfloat16 h = __float2bfloat16(fv[e]);
        __nv_bfloat16 l = __float2bfloat16(fv[e] - __bfloat162float(h));
        hi |= (U64)__bfloat16_as_ushort(h) << (16 * e);
        lo |= (U64)__bfloat16_as_ushort(l) << (16 * e);
    }
    *(U64*)(g_wtsm + t * 65536 + off)         = hi;
    *(U64*)(g_wtsm + t * 65536 + 32768 + off) = lo;
}

// ---------------------------------------------------------------------------
// Kernel 1: fused offset(18)+mask(9) 3x3 conv (unchanged, passing)
// ---------------------------------------------------------------------------
__global__ void k_offmask(const float* __restrict__ x,
                          const float* __restrict__ ow, const float* __restrict__ ob,
                          const float* __restrict__ mw, const float* __restrict__ mb) {
    __shared__ U64 ws2[27 * 16 * 9];
    int tid = threadIdx.x;
    int p0  = (blockIdx.x * 128 + tid) * 2;
    int b   = p0 / HWX;
    int rem = p0 - b * HWX;
    int h   = rem / WW;
    int w0  = rem - h * WW;

    U64 acc2[27];
#pragma unroll
    for (int oc = 0; oc < 27; ++oc) {
        float bv = (oc < 18) ? ob[oc] : mb[oc - 18];
        acc2[oc] = pk2(bv, bv);
    }
    int  yoff[3]; bool yok[3];
#pragma unroll
    for (int dy = 0; dy < 3; ++dy) { int yy = h - 1 + dy; yok[dy] = (yy >= 0) && (yy < HH); yoff[dy] = yy * WW; }
    int  xoff[4]; bool xok[4];
#pragma unroll
    for (int dxx = 0; dxx < 4; ++dxx) { int xx = w0 - 1 + dxx; xok[dxx] = (xx >= 0) && (xx < WW); xoff[dxx] = xx; }

    const float* xb0 = x + b * CHW;
    float xv[3][4], xvn[3][4];
#pragma unroll
    for (int dy = 0; dy < 3; ++dy)
#pragma unroll
        for (int dxx = 0; dxx < 4; ++dxx)
            xv[dy][dxx] = (yok[dy] && xok[dxx]) ? xb0[yoff[dy] + xoff[dxx]] : 0.f;

    for (int cc = 0; cc < 8; ++cc) {
        __syncthreads();
        for (int lin = tid; lin < 3888; lin += 128) {
            int oc = lin / 144;
            int r  = lin - oc * 144;
            float wv = (oc < 18) ? ow[oc * KTOT + cc * 144 + r]
                                 : mw[(oc - 18) * KTOT + cc * 144 + r];
            ws2[lin] = pk2(wv, wv);
        }
        __syncthreads();
        for (int c16 = 0; c16 < 16; ++c16) {
            int cg = cc * 16 + c16;
            if (cg < CC - 1) {
                const float* xb = xb0 + (cg + 1) * HWX;
#pragma unroll
                for (int dy = 0; dy < 3; ++dy)
#pragma unroll
                    for (int dxx = 0; dxx < 4; ++dxx)
                        xvn[dy][dxx] = (yok[dy] && xok[dxx]) ? xb[yoff[dy] + xoff[dxx]] : 0.f;
            }
            U64 xp[9];
#pragma unroll
            for (int ky = 0; ky < 3; ++ky)
#pragma unroll
                for (int kx = 0; kx < 3; ++kx)
                    xp[ky * 3 + kx] = pk2(xv[ky][kx], xv[ky][kx + 1]);
            const U64* wp = ws2 + c16 * 9;
#pragma unroll
            for (int oc = 0; oc < 27; ++oc)
#pragma unroll
                for (int k = 0; k < 9; ++k)
                    fma2(acc2[oc], wp[oc * 144 + k], xp[k]);
#pragma unroll
            for (int dy = 0; dy < 3; ++dy)
#pragma unroll
                for (int dxx = 0; dxx < 4; ++dxx)
                    xv[dy][dxx] = xvn[dy][dxx];
        }
    }
#pragma unroll
    for (int oc = 0; oc < 18; ++oc) {
        F2U cv; cv.u = acc2[oc];
        g_off[(b * 18 + oc) * HWX + rem]     = cv.f.x;
        g_off[(b * 18 + oc) * HWX + rem + 1] = cv.f.y;
    }
#pragma unroll
    for (int k = 0; k < 9; ++k) {
        F2U cv; cv.u = acc2[18 + k];
        g_mask[(b * 9 + k) * HWX + rem]     = 1.f / (1.f + expf(-cv.f.x));
        g_mask[(b * 9 + k) * HWX + rem + 1] = 1.f / (1.f + expf(-cv.f.y));
    }
}

// ---------------------------------------------------------------------------
// Kernel 2: pipelined deformable implicit GEMM via mma.sync (HMMA).
//   Block: 128 Co x 128 px; double-buffered A+B; one sync per K-chunk.
// ---------------------------------------------------------------------------
extern __shared__ __align__(1024) char smem_raw[];

// Pre-phase: issue 16 values x 4 tap LDGs into regs (kk0 = global k start).
__device__ __forceinline__ void gather_pre(const float* __restrict__ x,
                                           const int* __restrict__ piP,
                                           int kk0, int pxi, float xt[16][4]) {
    int c = kk0 / 9;
    int k = kk0 - 9 * c;
    int coff = c * HWX;
#pragma unroll
    for (int v = 0; v < 16; ++v) {
        int p = piP[k * 128 + pxi];
        int a0 = (p & 0x7FFFFF) + coff;
        int fx = (p >> 23) & 1;
        int dy = ((p >> 24) & 1) ? WW : 0;
        xt[v][0] = x[a0];
        xt[v][1] = x[a0 + fx];
        xt[v][2] = x[a0 + dy];
        xt[v][3] = x[a0 + dy + fx];
        if (++k == 9) { k = 0; coff += HWX; }
    }
}

// Post-phase: combine with pw, split to bf16 hi/lo, store swizzled.
__device__ __forceinline__ void gather_post(const float* __restrict__ pwP,
                                            int kk0, int klocal, int pxi,
                                            const float xt[16][4], char* Bbuf) {
    int c = kk0 / 9;
    int k = kk0 - 9 * c;
    unsigned rowoff  = (unsigned)(pxi >> 3) * 1024;
    unsigned rowbase = (pxi & 7) * 128;
    unsigned xorv    = (rowbase >> 3) & 0x70;
#pragma unroll
    for (int g = 0; g < 4; ++g) {
        U64 hv = 0, lv = 0;
#pragma unroll
        for (int e = 0; e < 4; ++e) {
            int v = g * 4 + e;
            float4 pw = *(const float4*)(pwP + (k * 128 + pxi) * 4);
            float val = pw.x * xt[v][0] + pw.y * xt[v][1]
                      + pw.z * xt[v][2] + pw.w * xt[v][3];
            __nv_bfloat16 vh = __float2bfloat16(val);
            __nv_bfloat16 vl = __float2bfloat16(val - __bfloat162float(vh));
            hv |= (U64)__bfloat16_as_ushort(vh) << (16 * e);
            lv |= (U64)__bfloat16_as_ushort(vl) << (16 * e);
            if (++k == 9) k = 0;
        }
        unsigned col = (unsigned)(klocal + g * 4) * 2;
        unsigned off = rowoff + ((rowbase + col) ^ xorv);
        *(U64*)(Bbuf + off)         = hv;
        *(U64*)(Bbuf + 16384 + off) = lv;
    }
}

__global__ __launch_bounds__(256, 1) void k_deform(const float* __restrict__ x,
                                                   const float* __restrict__ bias,
                                                   float* __restrict__ out) {
    char* sbase = smem_raw;
    int tid    = threadIdx.x;
    int wid    = tid >> 5;
    int lane   = tid & 31;
    int pbase  = blockIdx.x * 128;
    int coHalf = blockIdx.y;

    int*   piP = (int*)(sbase + OFF_PI);
    float* pwP = (float*)(sbase + OFF_PW);

    // ---- Prologue: per-(k, px) bilinear params ----
    for (int item = tid; item < 1152; item += 256) {
        int j = item & 127;
        int k = item >> 7;
        int pixel = pbase + j;
        int b   = pixel / HWX;
        int rem = pixel - b * HWX;
        int h   = rem / WW;
        int w   = rem - h * WW;
        float dyv = g_off[(b * 18 + 2 * k)     * HWX + rem];
        float dxv = g_off[(b * 18 + 2 * k + 1) * HWX + rem];
        float m   = g_mask[(b * 9 + k) * HWX + rem];
        int ky = k / 3, kx = k - ky * 3;
        float py = (float)(h - 1 + ky) + dyv;
        float px = (float)(w - 1 + kx) + dxv;
        float fy = floorf(py), fxx = floorf(px);
        int y0 = (int)fy, x0 = (int)fxx;
        float ly = py - fy, lx = px - fxx;
        float hy = 1.f - ly, hx = 1.f - lx;
        bool vy0 = (y0 >= 0)  && (y0 < HH);
        bool vy1 = (y0 >= -1) && (y0 < HH - 1);
        bool vx0 = (x0 >= 0)  && (x0 < WW);
        bool vx1 = (x0 >= -1) && (x0 < WW - 1);
        int y0c = min(max(y0, 0), HH - 1), y1c = min(max(y0 + 1, 0), HH - 1);
        int x0c = min(max(x0, 0), WW - 1), x1c = min(max(x0 + 1, 0), WW - 1);
        int p = (b * CHW + y0c * WW + x0c)
              | ((x1c - x0c) << 23) | ((y1c - y0c) << 24);
        piP[k * 128 + j] = p;
        float4 pw;
        pw.x = (vy0 && vx0) ? hy * hx * m : 0.f;
        pw.y = (vy0 && vx1) ? hy * lx * m : 0.f;
        pw.z = (vy1 && vx0) ? ly * hx * m : 0.f;
        pw.w = (vy1 && vx1) ? ly * lx * m : 0.f;
        *(float4*)(pwP + (k * 128 + j) * 4) = pw;
    }
    __syncthreads();

    float acc[4][4][4];
#pragma unroll
    for (int a = 0; a < 4; ++a)
#pragma unroll
        for (int b2 = 0; b2 < 4; ++b2)
#pragma unroll
            for (int c = 0; c < 4; ++c) acc[a][b2][c] = 0.f;

    // Warp tiling: 2 (m) x 4 (n)
    int m_base = (wid & 1) * 64;
    int n_base = (wid >> 1) * 32;

    int rA = m_base + (lane & 15);
    unsigned aRow = (unsigned)(rA >> 3) * 1024 + (rA & 7) * 128;
    unsigned aXor = (unsigned)(rA & 7) << 4;
    unsigned aKhi = (unsigned)(lane >> 4) * 16;
    int pB = n_base + ((lane >> 4) << 3) + (lane & 7);
    unsigned bRow = (unsigned)(pB >> 3) * 1024 + (pB & 7) * 128;
    unsigned bXor = (unsigned)(pB & 7) << 4;
    unsigned bKhi = (unsigned)((lane >> 3) & 1) * 16;

    unsigned sA0 = s2u(sbase + OFF_A0);
    unsigned sB0 = s2u(sbase + OFF_B0);

    int pxi = tid & 127;            // B-fill pixel
    int kh  = (tid >> 7) * 32;      // B-fill k offset within tile

    float xt[16][4];

    // ---- Prime buffer 0 ----
    {
        const unsigned char* gh = g_wtsm + coHalf * 16384;
#pragma unroll
        for (int q = 0; q < 4; ++q)
            cpa16(sA0 + tid * 64 + q * 16, gh + (size_t)tid * 64 + q * 16);
#pragma unroll
        for (int q = 0; q < 4; ++q)
            cpa16(sA0 + 16384 + tid * 64 + q * 16, gh + 32768 + (size_t)tid * 64 + q * 16);
        CP_COMMIT();
        gather_pre(x, piP, kh, pxi, xt);
        gather_post(pwP, kh, kh, pxi, xt, sbase + OFF_B0);
        gather_pre(x, piP, kh + 16, pxi, xt);
        gather_post(pwP, kh + 16, kh + 16, pxi, xt, sbase + OFF_B0);
        CP_WAIT0();
    }
    __syncthreads();

    for (int it = 0; it < NITER; ++it) {
        int cur = it & 1, nxt = cur ^ 1;
        bool pf = (it < NITER - 1);
        char* Bn = sbase + OFF_B0 + nxt * 32768;
        int kkn0 = (it + 1) * KC + kh;

        if (pf) {
            // A(it+1) via cp.async into A[nxt]
            const unsigned char* gh = g_wtsm + (it + 1) * 65536 + coHalf * 16384;
            unsigned sAn = sA0 + (unsigned)nxt * 32768;
#pragma unroll
            for (int q = 0; q < 4; ++q)
                cpa16(sAn + tid * 64 + q * 16, gh + (size_t)tid * 64 + q * 16);
#pragma unroll
            for (int q = 0; q < 4; ++q)
                cpa16(sAn + 16384 + tid * 64 + q * 16, gh + 32768 + (size_t)tid * 64 + q * 16);
            CP_COMMIT();
            // B(it+1) chunk0: issue gather loads
            gather_pre(x, piP, kkn0, pxi, xt);
        }

        unsigned sAhi = sA0 + (unsigned)cur * 32768;
        unsigned sAlo = sAhi + 16384;
        unsigned sBhi = sB0 + (unsigned)cur * 32768;
        unsigned sBlo = sBhi + 16384;

        // ---- MMA k16 = 0,1 ----
#pragma unroll
        for (int k16 = 0; k16 < 2; ++k16) {
            unsigned kb = (unsigned)k16 * 32;
            unsigned bOff = bRow + ((kb + bKhi) ^ bXor);
            unsigned bh[8], bl[8];
            LDSM4(bh[0], bh[1], bh[2], bh[3], sBhi + bOff);
            LDSM4(bh[4], bh[5], bh[6], bh[7], sBhi + bOff + 2048);
            LDSM4(bl[0], bl[1], bl[2], bl[3], sBlo + bOff);
            LDSM4(bl[4], bl[5], bl[6], bl[7], sBlo + bOff + 2048);
            unsigned aOffB = aRow + ((kb + aKhi) ^ aXor);
#pragma unroll
            for (int mg = 0; mg < 4; ++mg) {
                unsigned aOff = aOffB + (unsigned)mg * 2048;
                unsigned a0, a1, a2, a3;
                LDSM4(a0, a1, a2, a3, sAhi + aOff);
                MMA(acc[mg][0], a0, a1, a2, a3, bh[0], bh[1]);
                MMA(acc[mg][1], a0, a1, a2, a3, bh[2], bh[3]);
                MMA(acc[mg][2], a0, a1, a2, a3, bh[4], bh[5]);
                MMA(acc[mg][3], a0, a1, a2, a3, bh[6], bh[7]);
                MMA(acc[mg][0], a0, a1, a2, a3, bl[0], bl[1]);
                MMA(acc[mg][1], a0, a1, a2, a3, bl[2], bl[3]);
                MMA(acc[mg][2], a0, a1, a2, a3, bl[4], bl[5]);
                MMA(acc[mg][3], a0, a1, a2, a3, bl[6], bl[7]);
                LDSM4(a0, a1, a2, a3, sAlo + aOff);
                MMA(acc[mg][0], a0, a1, a2, a3, bh[0], bh[1]);
                MMA(acc[mg][1], a0, a1, a2, a3, bh[2], bh[3]);
                MMA(acc[mg][2], a0, a1, a2, a3, bh[4], bh[5]);
                MMA(acc[mg][3], a0, a1, a2, a3, bh[6], bh[7]);
            }
        }

        if (pf) {
            gather_post(pwP, kkn0, kh, pxi, xt, Bn);
            gather_pre(x, piP, kkn0 + 16, pxi, xt);
        }

        // ---- MMA k16 = 2,3 ----
#pragma unroll
        for (int k16 = 2; k16 < 4; ++k16) {
            unsigned kb = (unsigned)k16 * 32;
            unsigned bOff = bRow + ((kb + bKhi) ^ bXor);
            unsigned bh[8], bl[8];
            LDSM4(bh[0], bh[1], bh[2], bh[3], sBhi + bOff);
            LDSM4(bh[4], bh[5], bh[6], bh[7], sBhi + bOff + 2048);
            LDSM4(bl[0], bl[1], bl[2], bl[3], sBlo + bOff);
            LDSM4(bl[4], bl[5], bl[6], bl[7], sBlo + bOff + 2048);
            unsigned aOffB = aRow + ((kb + aKhi) ^ aXor);
#pragma unroll
            for (int mg = 0; mg < 4; ++mg) {
                unsigned aOff = aOffB + (unsigned)mg * 2048;
                unsigned a0, a1, a2, a3;
                LDSM4(a0, a1, a2, a3, sAhi + aOff);
                MMA(acc[mg][0], a0, a1, a2, a3, bh[0], bh[1]);
                MMA(acc[mg][1], a0, a1, a2, a3, bh[2], bh[3]);
                MMA(acc[mg][2], a0, a1, a2, a3, bh[4], bh[5]);
                MMA(acc[mg][3], a0, a1, a2, a3, bh[6], bh[7]);
                MMA(acc[mg][0], a0, a1, a2, a3, bl[0], bl[1]);
                MMA(acc[mg][1], a0, a1, a2, a3, bl[2], bl[3]);
                MMA(acc[mg][2], a0, a1, a2, a3, bl[4], bl[5]);
                MMA(acc[mg][3], a0, a1, a2, a3, bl[6], bl[7]);
                LDSM4(a0, a1, a2, a3, sAlo + aOff);
                MMA(acc[mg][0], a0, a1, a2, a3, bh[0], bh[1]);
                MMA(acc[mg][1], a0, a1, a2, a3, bh[2], bh[3]);
                MMA(acc[mg][2], a0, a1, a2, a3, bh[4], bh[5]);
                MMA(acc[mg][3], a0, a1, a2, a3, bh[6], bh[7]);
            }
        }

        if (pf) {
            gather_post(pwP, kkn0 + 16, kh + 16, pxi, xt, Bn);
            CP_WAIT0();
        }
        __syncthreads();
    }

    // ---- Epilogue: bias + direct stores (mma D-fragment layout) ----
    {
        int bI  = pbase / HWX;
        int rem = pbase - bI * HWX;
#pragma unroll
        for (int mg = 0; mg < 4; ++mg) {
            int o0 = coHalf * 128 + m_base + mg * 16 + (lane >> 2);
            float bv0 = bias[o0];
            float bv1 = bias[o0 + 8];
            float* base0 = out + (size_t)(bI * CO + o0) * HWX + rem;
            float* base1 = base0 + (size_t)8 * HWX;
#pragma unroll
            for (int ng = 0; ng < 4; ++ng) {
                int c = n_base + ng * 8 + (lane & 3) * 2;
                float2 v0 = make_float2(acc[mg][ng][0] + bv0, acc[mg][ng][1] + bv0);
                float2 v1 = make_float2(acc[mg][ng][2] + bv1, acc[mg][ng][3] + bv1);
                *(float2*)(base0 + c) = v0;
                *(float2*)(base1 + c) = v1;
            }
        }
    }
}

// Position-2 filler so ncu's fixed capture slot (index 5, pre-offset 2) lands
// on k_deform at position 3.
__global__ void k_nop() {}

// ---------------------------------------------------------------------------
extern "C" void kernel_launch(void* const* d_in, const int* in_sizes, int n_in,
                              void* d_out, int out_size) {
    const float* x      = (const float*)d_in[0];
    const float* weight = (const float*)d_in[1];
    const float* bias   = (const float*)d_in[2];
    const float* ow     = (const float*)d_in[3];
    const float* ob     = (const float*)d_in[4];
    const float* mw     = (const float*)d_in[5];
    const float* mb     = (const float*)d_in[6];
    float* out = (float*)d_out;

    cudaFuncSetAttribute(k_deform, cudaFuncAttributeMaxDynamicSharedMemorySize,
                         SMEM_SZ);

    k_wt<<<288, 256>>>(weight);
    k_offmask<<<BB * HWX / 256, 128>>>(x, ow, ob, mw, mb);
    k_nop<<<1, 32>>>();
    dim3 grid(BB * HWX / 128, 2);
    k_deform<<<grid, 256, SMEM_SZ>>>(x, bias, out);
}

// round 8
// speedup vs baseline: 1.0052x; 1.0052x over previous
#include <cuda_runtime.h>
#include <cuda_bf16.h>
#include <math.h>
#include <stdint.h>

typedef unsigned long long U64;

// Problem constants
#define BB   4
#define CC   128
#define HH   96
#define WW   96
#define HWX  (HH*WW)          // 9216
#define CHW  (CC*HWX)         // 1179648
#define CO   256
#define KTOT (CC*9)           // 1152
#define NITER 18
#define KC    64              // K floats per iter

// Scratch (device globals)
__device__ float g_off [BB*18*HWX];
__device__ float g_mask[BB*9*HWX];
// Pre-split, pre-swizzled A tiles: [18 iters][hi 32KB | lo 32KB], SW128 rows.
__device__ __align__(16) unsigned char g_wtsm[NITER * 65536];

// SMEM layout (dynamic), occ-1 double buffered
#define OFF_A0 0          // A buf0: hi 16384 | lo 16384 (this block's Co half)
#define OFF_A1 32768
#define OFF_B0 65536      // B buf0: hi 16384 | lo 16384
#define OFF_B1 98304
#define OFF_PI 131072     // 9*128*4  = 4608
#define OFF_PW 135680     // 9*128*16 = 18432
#define SMEM_SZ 154112

union F2U { U64 u; float2 f; };

__device__ __forceinline__ U64 pk2(float a, float b) {
    U64 r; asm("mov.b64 %0, {%1, %2};" : "=l"(r) : "f"(a), "f"(b)); return r;
}
__device__ __forceinline__ void fma2(U64 &d, U64 a, U64 b) {
    asm("fma.rn.f32x2 %0, %1, %2, %3;" : "=l"(d) : "l"(a), "l"(b), "l"(d));
}
__device__ __forceinline__ unsigned s2u(const void* p) {
    return (unsigned)__cvta_generic_to_shared(p);
}
__device__ __forceinline__ void cpa16(unsigned dst, const void* src) {
    asm volatile("cp.async.cg.shared.global [%0], [%1], 16;" :: "r"(dst), "l"(src));
}
#define CP_COMMIT()  asm volatile("cp.async.commit_group;" ::: "memory")
#define CP_WAIT0()   asm volatile("cp.async.wait_group 0;" ::: "memory")

#define LDSM4(r0, r1, r2, r3, addr) \
    asm volatile("ldmatrix.sync.aligned.m8n8.x4.shared.b16 {%0,%1,%2,%3}, [%4];" \
        : "=r"(r0), "=r"(r1), "=r"(r2), "=r"(r3) : "r"(addr))

#define MMA(d, a0, a1, a2, a3, b0, b1) \
    asm volatile("mma.sync.aligned.m16n8k16.row.col.f32.bf16.bf16.f32 " \
        "{%0,%1,%2,%3}, {%4,%5,%6,%7}, {%8,%9}, {%0,%1,%2,%3};" \
        : "+f"((d)[0]), "+f"((d)[1]), "+f"((d)[2]), "+f"((d)[3]) \
        : "r"(a0), "r"(a1), "r"(a2), "r"(a3), "r"(b0), "r"(b1))

// ---------------------------------------------------------------------------
// Kernel 0: pre-split weights into bf16 hi/lo, pre-swizzled SW128 tile images.
// ---------------------------------------------------------------------------
__global__ void k_wt(const float* __restrict__ w) {
    int i = blockIdx.x * 256 + threadIdx.x;
    int o  = i / 288;
    int r4 = (i - o * 288) * 4;
    float4 wv = *(const float4*)(w + o * KTOT + r4);
    int t  = r4 >> 6;
    int kk = r4 & 63;
    unsigned rowbase = (o & 7) * 128;
    unsigned off = (unsigned)(o >> 3) * 1024
                 + ((rowbase + kk * 2) ^ ((rowbase >> 3) & 0x70));
    const float* fv = (const float*)&wv;
    U64 hi = 0, lo = 0;
#pragma unroll
    for (int e = 0; e < 4; ++e) {
        __nv_bfloat16 h = __float2bfloat16(fv[e]);
        __nv_bfloat16 l = __float2bfloat16(fv[e] - __bfloat162float(h));
        hi |= (U64)__bfloat16_as_ushort(h) << (16 * e);
        lo |= (U64)__bfloat16_as_ushort(l) << (16 * e);
    }
    *(U64*)(g_wtsm + t * 65536 + off)         = hi;
    *(U64*)(g_wtsm + t * 65536 + 32768 + off) = lo;
}

// ---------------------------------------------------------------------------
// Kernel 1: fused offset(18)+mask(9) 3x3 conv (unchanged, passing)
// ---------------------------------------------------------------------------
__global__ void k_offmask(const float* __restrict__ x,
                          const float* __restrict__ ow, const float* __restrict__ ob,
                          const float* __restrict__ mw, const float* __restrict__ mb) {
    __shared__ U64 ws2[27 * 16 * 9];
    int tid = threadIdx.x;
    int p0  = (blockIdx.x * 128 + tid) * 2;
    int b   = p0 / HWX;
    int rem = p0 - b * HWX;
    int h   = rem / WW;
    int w0  = rem - h * WW;

    U64 acc2[27];
#pragma unroll
    for (int oc = 0; oc < 27; ++oc) {
        float bv = (oc < 18) ? ob[oc] : mb[oc - 18];
        acc2[oc] = pk2(bv, bv);
    }
    int  yoff[3]; bool yok[3];
#pragma unroll
    for (int dy = 0; dy < 3; ++dy) { int yy = h - 1 + dy; yok[dy] = (yy >= 0) && (yy < HH); yoff[dy] = yy * WW; }
    int  xoff[4]; bool xok[4];
#pragma unroll
    for (int dxx = 0; dxx < 4; ++dxx) { int xx = w0 - 1 + dxx; xok[dxx] = (xx >= 0) && (xx < WW); xoff[dxx] = xx; }

    const float* xb0 = x + b * CHW;
    float xv[3][4], xvn[3][4];
#pragma unroll
    for (int dy = 0; dy < 3; ++dy)
#pragma unroll
        for (int dxx = 0; dxx < 4; ++dxx)
            xv[dy][dxx] = (yok[dy] && xok[dxx]) ? xb0[yoff[dy] + xoff[dxx]] : 0.f;

    for (int cc = 0; cc < 8; ++cc) {
        __syncthreads();
        for (int lin = tid; lin < 3888; lin += 128) {
            int oc = lin / 144;
            int r  = lin - oc * 144;
            float wv = (oc < 18) ? ow[oc * KTOT + cc * 144 + r]
                                 : mw[(oc - 18) * KTOT + cc * 144 + r];
            ws2[lin] = pk2(wv, wv);
        }
        __syncthreads();
        for (int c16 = 0; c16 < 16; ++c16) {
            int cg = cc * 16 + c16;
            if (cg < CC - 1) {
                const float* xb = xb0 + (cg + 1) * HWX;
#pragma unroll
                for (int dy = 0; dy < 3; ++dy)
#pragma unroll
                    for (int dxx = 0; dxx < 4; ++dxx)
                        xvn[dy][dxx] = (yok[dy] && xok[dxx]) ? xb[yoff[dy] + xoff[dxx]] : 0.f;
            }
            U64 xp[9];
#pragma unroll
            for (int ky = 0; ky < 3; ++ky)
#pragma unroll
                for (int kx = 0; kx < 3; ++kx)
                    xp[ky * 3 + kx] = pk2(xv[ky][kx], xv[ky][kx + 1]);
            const U64* wp = ws2 + c16 * 9;
#pragma unroll
            for (int oc = 0; oc < 27; ++oc)
#pragma unroll
                for (int k = 0; k < 9; ++k)
                    fma2(acc2[oc], wp[oc * 144 + k], xp[k]);
#pragma unroll
            for (int dy = 0; dy < 3; ++dy)
#pragma unroll
                for (int dxx = 0; dxx < 4; ++dxx)
                    xv[dy][dxx] = xvn[dy][dxx];
        }
    }
#pragma unroll
    for (int oc = 0; oc < 18; ++oc) {
        F2U cv; cv.u = acc2[oc];
        g_off[(b * 18 + oc) * HWX + rem]     = cv.f.x;
        g_off[(b * 18 + oc) * HWX + rem + 1] = cv.f.y;
    }
#pragma unroll
    for (int k = 0; k < 9; ++k) {
        F2U cv; cv.u = acc2[18 + k];
        g_mask[(b * 9 + k) * HWX + rem]     = 1.f / (1.f + expf(-cv.f.x));
        g_mask[(b * 9 + k) * HWX + rem + 1] = 1.f / (1.f + expf(-cv.f.y));
    }
}

// ---------------------------------------------------------------------------
// Kernel 2: pipelined deformable implicit GEMM via mma.sync (HMMA).
//   Block: 128 Co x 128 px; double-buffered A+B; one sync per K-chunk.
// ---------------------------------------------------------------------------
extern __shared__ __align__(1024) char smem_raw[];

// Pre-phase: issue 16 values x 4 tap LDGs into regs (kk0 = global k start).
__device__ __forceinline__ void gather_pre(const float* __restrict__ x,
                                           const int* __restrict__ piP,
                                           int kk0, int pxi, float xt[16][4]) {
    int c = kk0 / 9;
    int k = kk0 - 9 * c;
    int coff = c * HWX;
#pragma unroll
    for (int v = 0; v < 16; ++v) {
        int p = piP[k * 128 + pxi];
        int a0 = (p & 0x7FFFFF) + coff;
        int fx = (p >> 23) & 1;
        int dy = ((p >> 24) & 1) ? WW : 0;
        xt[v][0] = x[a0];
        xt[v][1] = x[a0 + fx];
        xt[v][2] = x[a0 + dy];
        xt[v][3] = x[a0 + dy + fx];
        if (++k == 9) { k = 0; coff += HWX; }
    }
}

// Post-phase: combine with pw, split to bf16 hi/lo, store swizzled.
__device__ __forceinline__ void gather_post(const float* __restrict__ pwP,
                                            int kk0, int klocal, int pxi,
                                            const float xt[16][4], char* Bbuf) {
    int c = kk0 / 9;
    int k = kk0 - 9 * c;
    unsigned rowoff  = (unsigned)(pxi >> 3) * 1024;
    unsigned rowbase = (pxi & 7) * 128;
    unsigned xorv    = (rowbase >> 3) & 0x70;
#pragma unroll
    for (int g = 0; g < 4; ++g) {
        U64 hv = 0, lv = 0;
#pragma unroll
        for (int e = 0; e < 4; ++e) {
            int v = g * 4 + e;
            float4 pw = *(const float4*)(pwP + (k * 128 + pxi) * 4);
            float val = pw.x * xt[v][0] + pw.y * xt[v][1]
                      + pw.z * xt[v][2] + pw.w * xt[v][3];
            __nv_bfloat16 vh = __float2bfloat16(val);
            __nv_bfloat16 vl = __float2bfloat16(val - __bfloat162float(vh));
            hv |= (U64)__bfloat16_as_ushort(vh) << (16 * e);
            lv |= (U64)__bfloat16_as_ushort(vl) << (16 * e);
            if (++k == 9) k = 0;
        }
        unsigned col = (unsigned)(klocal + g * 4) * 2;
        unsigned off = rowoff + ((rowbase + col) ^ xorv);
        *(U64*)(Bbuf + off)         = hv;
        *(U64*)(Bbuf + 16384 + off) = lv;
    }
}

__global__ __launch_bounds__(256, 1) void k_deform(const float* __restrict__ x,
                                                   const float* __restrict__ bias,
                                                   float* __restrict__ out) {
    char* sbase = smem_raw;
    int tid    = threadIdx.x;
    int wid    = tid >> 5;
    int lane   = tid & 31;
    int pbase  = blockIdx.x * 128;
    int coHalf = blockIdx.y;

    int*   piP = (int*)(sbase + OFF_PI);
    float* pwP = (float*)(sbase + OFF_PW);

    // ---- Prologue: per-(k, px) bilinear params ----
    for (int item = tid; item < 1152; item += 256) {
        int j = item & 127;
        int k = item >> 7;
        int pixel = pbase + j;
        int b   = pixel / HWX;
        int rem = pixel - b * HWX;
        int h   = rem / WW;
        int w   = rem - h * WW;
        float dyv = g_off[(b * 18 + 2 * k)     * HWX + rem];
        float dxv = g_off[(b * 18 + 2 * k + 1) * HWX + rem];
        float m   = g_mask[(b * 9 + k) * HWX + rem];
        int ky = k / 3, kx = k - ky * 3;
        float py = (float)(h - 1 + ky) + dyv;
        float px = (float)(w - 1 + kx) + dxv;
        float fy = floorf(py), fxx = floorf(px);
        int y0 = (int)fy, x0 = (int)fxx;
        float ly = py - fy, lx = px - fxx;
        float hy = 1.f - ly, hx = 1.f - lx;
        bool vy0 = (y0 >= 0)  && (y0 < HH);
        bool vy1 = (y0 >= -1) && (y0 < HH - 1);
        bool vx0 = (x0 >= 0)  && (x0 < WW);
        bool vx1 = (x0 >= -1) && (x0 < WW - 1);
        int y0c = min(max(y0, 0), HH - 1), y1c = min(max(y0 + 1, 0), HH - 1);
        int x0c = min(max(x0, 0), WW - 1), x1c = min(max(x0 + 1, 0), WW - 1);
        int p = (b * CHW + y0c * WW + x0c)
              | ((x1c - x0c) << 23) | ((y1c - y0c) << 24);
        piP[k * 128 + j] = p;
        float4 pw;
        pw.x = (vy0 && vx0) ? hy * hx * m : 0.f;
        pw.y = (vy0 && vx1) ? hy * lx * m : 0.f;
        pw.z = (vy1 && vx0) ? ly * hx * m : 0.f;
        pw.w = (vy1 && vx1) ? ly * lx * m : 0.f;
        *(float4*)(pwP + (k * 128 + j) * 4) = pw;
    }
    __syncthreads();

    float acc[4][4][4];
#pragma unroll
    for (int a = 0; a < 4; ++a)
#pragma unroll
        for (int b2 = 0; b2 < 4; ++b2)
#pragma unroll
            for (int c = 0; c < 4; ++c) acc[a][b2][c] = 0.f;

    // Warp tiling: 2 (m) x 4 (n)
    int m_base = (wid & 1) * 64;
    int n_base = (wid >> 1) * 32;

    int rA = m_base + (lane & 15);
    unsigned aRow = (unsigned)(rA >> 3) * 1024 + (rA & 7) * 128;
    unsigned aXor = (unsigned)(rA & 7) << 4;
    unsigned aKhi = (unsigned)(lane >> 4) * 16;
    int pB = n_base + ((lane >> 4) << 3) + (lane & 7);
    unsigned bRow = (unsigned)(pB >> 3) * 1024 + (pB & 7) * 128;
    unsigned bXor = (unsigned)(pB & 7) << 4;
    unsigned bKhi = (unsigned)((lane >> 3) & 1) * 16;

    unsigned sA0 = s2u(sbase + OFF_A0);
    unsigned sB0 = s2u(sbase + OFF_B0);

    int pxi = tid & 127;            // B-fill pixel
    int kh  = (tid >> 7) * 32;      // B-fill k offset within tile

    float xt[16][4];

    // ---- Prime buffer 0 ----
    {
        const unsigned char* gh = g_wtsm + coHalf * 16384;
#pragma unroll
        for (int q = 0; q < 4; ++q)
            cpa16(sA0 + tid * 64 + q * 16, gh + (size_t)tid * 64 + q * 16);
#pragma unroll
        for (int q = 0; q < 4; ++q)
            cpa16(sA0 + 16384 + tid * 64 + q * 16, gh + 32768 + (size_t)tid * 64 + q * 16);
        CP_COMMIT();
        gather_pre(x, piP, kh, pxi, xt);
        gather_post(pwP, kh, kh, pxi, xt, sbase + OFF_B0);
        gather_pre(x, piP, kh + 16, pxi, xt);
        gather_post(pwP, kh + 16, kh + 16, pxi, xt, sbase + OFF_B0);
        CP_WAIT0();
    }
    __syncthreads();

    for (int it = 0; it < NITER; ++it) {
        int cur = it & 1, nxt = cur ^ 1;
        bool pf = (it < NITER - 1);
        char* Bn = sbase + OFF_B0 + nxt * 32768;
        int kkn0 = (it + 1) * KC + kh;

        if (pf) {
            // A(it+1) via cp.async into A[nxt]
            const unsigned char* gh = g_wtsm + (it + 1) * 65536 + coHalf * 16384;
            unsigned sAn = sA0 + (unsigned)nxt * 32768;
#pragma unroll
            for (int q = 0; q < 4; ++q)
                cpa16(sAn + tid * 64 + q * 16, gh + (size_t)tid * 64 + q * 16);
#pragma unroll
            for (int q = 0; q < 4; ++q)
                cpa16(sAn + 16384 + tid * 64 + q * 16, gh + 32768 + (size_t)tid * 64 + q * 16);
            CP_COMMIT();
            // B(it+1) chunk0: issue gather loads
            gather_pre(x, piP, kkn0, pxi, xt);
        }

        unsigned sAhi = sA0 + (unsigned)cur * 32768;
        unsigned sAlo = sAhi + 16384;
        unsigned sBhi = sB0 + (unsigned)cur * 32768;
        unsigned sBlo = sBhi + 16384;

        // ---- MMA k16 = 0,1 ----
#pragma unroll
        for (int k16 = 0; k16 < 2; ++k16) {
            unsigned kb = (unsigned)k16 * 32;
            unsigned bOff = bRow + ((kb + bKhi) ^ bXor);
            unsigned bh[8], bl[8];
            LDSM4(bh[0], bh[1], bh[2], bh[3], sBhi + bOff);
            LDSM4(bh[4], bh[5], bh[6], bh[7], sBhi + bOff + 2048);
            LDSM4(bl[0], bl[1], bl[2], bl[3], sBlo + bOff);
            LDSM4(bl[4], bl[5], bl[6], bl[7], sBlo + bOff + 2048);
            unsigned aOffB = aRow + ((kb + aKhi) ^ aXor);
#pragma unroll
            for (int mg = 0; mg < 4; ++mg) {
                unsigned aOff = aOffB + (unsigned)mg * 2048;
                unsigned a0, a1, a2, a3;
                LDSM4(a0, a1, a2, a3, sAhi + aOff);
                MMA(acc[mg][0], a0, a1, a2, a3, bh[0], bh[1]);
                MMA(acc[mg][1], a0, a1, a2, a3, bh[2], bh[3]);
                MMA(acc[mg][2], a0, a1, a2, a3, bh[4], bh[5]);
                MMA(acc[mg][3], a0, a1, a2, a3, bh[6], bh[7]);
                MMA(acc[mg][0], a0, a1, a2, a3, bl[0], bl[1]);
                MMA(acc[mg][1], a0, a1, a2, a3, bl[2], bl[3]);
                MMA(acc[mg][2], a0, a1, a2, a3, bl[4], bl[5]);
                MMA(acc[mg][3], a0, a1, a2, a3, bl[6], bl[7]);
                LDSM4(a0, a1, a2, a3, sAlo + aOff);
                MMA(acc[mg][0], a0, a1, a2, a3, bh[0], bh[1]);
                MMA(acc[mg][1], a0, a1, a2, a3, bh[2], bh[3]);
                MMA(acc[mg][2], a0, a1, a2, a3, bh[4], bh[5]);
                MMA(acc[mg][3], a0, a1, a2, a3, bh[6], bh[7]);
            }
        }

        if (pf) {
            gather_post(pwP, kkn0, kh, pxi, xt, Bn);
            gather_pre(x, piP, kkn0 + 16, pxi, xt);
        }

        // ---- MMA k16 = 2,3 ----
#pragma unroll
        for (int k16 = 2; k16 < 4; ++k16) {
            unsigned kb = (unsigned)k16 * 32;
            unsigned bOff = bRow + ((kb + bKhi) ^ bXor);
            unsigned bh[8], bl[8];
            LDSM4(bh[0], bh[1], bh[2], bh[3], sBhi + bOff);
            LDSM4(bh[4], bh[5], bh[6], bh[7], sBhi + bOff + 2048);
            LDSM4(bl[0], bl[1], bl[2], bl[3], sBlo + bOff);
            LDSM4(bl[4], bl[5], bl[6], bl[7], sBlo + bOff + 2048);
            unsigned aOffB = aRow + ((kb + aKhi) ^ aXor);
#pragma unroll
            for (int mg = 0; mg < 4; ++mg) {
                unsigned aOff = aOffB + (unsigned)mg * 2048;
                unsigned a0, a1, a2, a3;
                LDSM4(a0, a1, a2, a3, sAhi + aOff);
                MMA(acc[mg][0], a0, a1, a2, a3, bh[0], bh[1]);
                MMA(acc[mg][1], a0, a1, a2, a3, bh[2], bh[3]);
                MMA(acc[mg][2], a0, a1, a2, a3, bh[4], bh[5]);
                MMA(acc[mg][3], a0, a1, a2, a3, bh[6], bh[7]);
                MMA(acc[mg][0], a0, a1, a2, a3, bl[0], bl[1]);
                MMA(acc[mg][1], a0, a1, a2, a3, bl[2], bl[3]);
                MMA(acc[mg][2], a0, a1, a2, a3, bl[4], bl[5]);
                MMA(acc[mg][3], a0, a1, a2, a3, bl[6], bl[7]);
                LDSM4(a0, a1, a2, a3, sAlo + aOff);
                MMA(acc[mg][0], a0, a1, a2, a3, bh[0], bh[1]);
                MMA(acc[mg][1], a0, a1, a2, a3, bh[2], bh[3]);
                MMA(acc[mg][2], a0, a1, a2, a3, bh[4], bh[5]);
                MMA(acc[mg][3], a0, a1, a2, a3, bh[6], bh[7]);
            }
        }

        if (pf) {
            gather_post(pwP, kkn0 + 16, kh + 16, pxi, xt, Bn);
            CP_WAIT0();
        }
        __syncthreads();
    }

    // ---- Epilogue: bias + direct stores (mma D-fragment layout) ----
    {
        int bI  = pbase / HWX;
        int rem = pbase - bI * HWX;
#pragma unroll
        for (int mg = 0; mg < 4; ++mg) {
            int o0 = coHalf * 128 + m_base + mg * 16 + (lane >> 2);
            float bv0 = bias[o0];
            float bv1 = bias[o0 + 8];
            float* base0 = out + (size_t)(bI * CO + o0) * HWX + rem;
            float* base1 = base0 + (size_t)8 * HWX;
#pragma unroll
            for (int ng = 0; ng < 4; ++ng) {
                int c = n_base + ng * 8 + (lane & 3) * 2;
                float2 v0 = make_float2(acc[mg][ng][0] + bv0, acc[mg][ng][1] + bv0);
                float2 v1 = make_float2(acc[mg][ng][2] + bv1, acc[mg][ng][3] + bv1);
                *(float2*)(base0 + c) = v0;
                *(float2*)(base1 + c) = v1;
            }
        }
    }
}

// Position-2 filler so ncu's fixed capture slot (index 5, pre-offset 2) lands
// on k_deform at position 3.
__global__ void k_nop() {}

// ---------------------------------------------------------------------------
extern "C" void kernel_launch(void* const* d_in, const int* in_sizes, int n_in,
                              void* d_out, int out_size) {
    const float* x      = (const float*)d_in[0];
    const float* weight = (const float*)d_in[1];
    const float* bias   = (const float*)d_in[2];
    const float* ow     = (const float*)d_in[3];
    const float* ob     = (const float*)d_in[4];
    const float* mw     = (const float*)d_in[5];
    const float* mb     = (const float*)d_in[6];
    float* out = (float*)d_out;

    cudaFuncSetAttribute(k_deform, cudaFuncAttributeMaxDynamicSharedMemorySize,
                         SMEM_SZ);

    k_wt<<<288, 256>>>(weight);
    k_offmask<<<BB * HWX / 256, 128>>>(x, ow, ob, mw, mb);
    k_nop<<<1, 32>>>();
    dim3 grid(BB * HWX / 128, 2);
    k_deform<<<grid, 256, SMEM_SZ>>>(x, bias, out);
}